// round 2
// baseline (speedup 1.0000x reference)
#include <cuda_runtime.h>
#include <cstdint>

// Problem-fixed sizes (N=100000, E=1600000, F: 128 -> 128 -> 64)
#define NMAX 100000

// Scratch (static __device__ arrays; no allocation APIs allowed)
__device__ float    g_S2[NMAX * 128];   // spmm1 accumulator (layer-1 pre-activation input)
__device__ float    g_S1[NMAX * 64];    // z = dropout(relu(S2@W1+b1)) @ W2
__device__ unsigned g_mask[NMAX * 4];   // packed keep bits, 128 bits per node

// ---------------------------------------------------------------------------
// Vector atomic reduction (sm_90+): 16B single L2 RMW transaction, no return.
__device__ __forceinline__ void red_add_v4(float4* p, float a, float b, float c, float d) {
    asm volatile("red.global.add.v4.f32 [%0], {%1,%2,%3,%4};"
                 :: "l"(p), "f"(a), "f"(b), "f"(c), "f"(d) : "memory");
}

// ---------------------------------------------------------------------------
// JAX threefry2x32 with key = (0, 42)   [jax.random.key(42)]
__device__ __forceinline__ uint2 tf2x32(unsigned c0, unsigned c1) {
    const unsigned ks0 = 0u, ks1 = 42u;
    const unsigned ks2 = ks0 ^ ks1 ^ 0x1BD11BDAu;
    unsigned x0 = c0 + ks0, x1 = c1 + ks1;
#define TFR(r) { x0 += x1; x1 = (x1 << (r)) | (x1 >> (32 - (r))); x1 ^= x0; }
    TFR(13) TFR(15) TFR(26) TFR(6)   x0 += ks1; x1 += ks2 + 1u;
    TFR(17) TFR(29) TFR(16) TFR(24)  x0 += ks2; x1 += ks0 + 2u;
    TFR(13) TFR(15) TFR(26) TFR(6)   x0 += ks0; x1 += ks1 + 3u;
    TFR(17) TFR(29) TFR(16) TFR(24)  x0 += ks1; x1 += ks2 + 4u;
    TFR(13) TFR(15) TFR(26) TFR(6)   x0 += ks2; x1 += ks0 + 5u;
#undef TFR
    return make_uint2(x0, x1);
}

// JAX partitionable threefry path (default since JAX 0.4.30):
//   counts = iota(uint64, size); bits1,bits2 = threefry2x32(key, counts>>32, counts_lo)
//   bits(32-bit) = bits1 ^ bits2
// Our size (N*128 = 12.8M) < 2^32 so the hi counter word is 0: element i uses
// tf2x32(0, i). keep = uniform < 0.5  <=>  MSB(bits) == 0
// (u = bitcast(bits>>9 | 0x3f800000) - 1 < 0.5 <=> bits < 2^31).
__global__ __launch_bounds__(256) void mask_kernel(int nwords) {
    int t = blockIdx.x * blockDim.x + threadIdx.x;
    if (t >= nwords) return;
    unsigned base = (unsigned)t * 32u;
    unsigned w = 0u;
#pragma unroll 8
    for (int j = 0; j < 32; ++j) {
        uint2 y = tf2x32(0u, base + j);
        w |= ((~(y.x ^ y.y)) >> 31) << j;   // keep iff MSB(y0^y1)==0
    }
    g_mask[t] = w;
}

// ---------------------------------------------------------------------------
__global__ __launch_bounds__(256) void zero_s2_kernel(int n4) {
    int i = blockIdx.x * blockDim.x + threadIdx.x;
    if (i < n4) ((float4*)g_S2)[i] = make_float4(0.f, 0.f, 0.f, 0.f);
}

// d_out = broadcast(b2): bias of layer 2 folded into output init; spmm2 then
// atomically accumulates directly into d_out.
__global__ __launch_bounds__(256) void init_out_kernel(float4* __restrict__ out4,
                                                       const float* __restrict__ b2, int n) {
    int i = blockIdx.x * blockDim.x + threadIdx.x;
    if (i >= n * 16) return;
    out4[i] = __ldg(((const float4*)b2) + (i & 15));
}

// ---------------------------------------------------------------------------
// spmm1: S2[dst] += w * x[src]   (128 features; 1 warp = 1 edge per iteration)
__global__ __launch_bounds__(256) void spmm128_kernel(const float4* __restrict__ x4,
                                                      const float* __restrict__ ew,
                                                      const int* __restrict__ src,
                                                      const int* __restrict__ dst, int E) {
    float4* out4 = (float4*)g_S2;
    int lane = threadIdx.x & 31;
    long warp = ((long)blockIdx.x * blockDim.x + threadIdx.x) >> 5;
    int e0 = (int)(warp * 32);
    if (e0 >= E) return;
    int e = e0 + lane;
    int s = 0, d = 0; float w = 0.f;
    if (e < E) { s = __ldg(&src[e]); d = __ldg(&dst[e]); w = __ldg(&ew[e]); }

    // 1-deep software pipeline: prefetch next gather while reducing current.
    int s0 = __shfl_sync(0xffffffffu, s, 0);
    float4 v = __ldg(&x4[(size_t)s0 * 32 + lane]);
#pragma unroll 4
    for (int j = 0; j < 32; ++j) {
        int   dj = __shfl_sync(0xffffffffu, d, j);
        float wj = __shfl_sync(0xffffffffu, w, j);
        float4 cur = v;
        if (j < 31) {
            int sn = __shfl_sync(0xffffffffu, s, j + 1);
            v = __ldg(&x4[(size_t)sn * 32 + lane]);
        }
        red_add_v4(&out4[(size_t)dj * 32 + lane], cur.x * wj, cur.y * wj, cur.z * wj, cur.w * wj);
    }
}

// spmm2: d_out[dst] += w * z[src]   (64 features; half-warp per edge, 2 edges/iter)
__global__ __launch_bounds__(256) void spmm64_kernel(const float* __restrict__ ew,
                                                     const int* __restrict__ src,
                                                     const int* __restrict__ dst,
                                                     float4* __restrict__ out4, int E) {
    const float4* h4 = (const float4*)g_S1;
    int lane = threadIdx.x & 31;
    long warp = ((long)blockIdx.x * blockDim.x + threadIdx.x) >> 5;
    int e0 = (int)(warp * 32);
    if (e0 >= E) return;
    int e = e0 + lane;
    int s = 0, d = 0; float w = 0.f;
    if (e < E) { s = __ldg(&src[e]); d = __ldg(&dst[e]); w = __ldg(&ew[e]); }
    int half = lane >> 4, fl = lane & 15;
#pragma unroll 4
    for (int j = 0; j < 16; ++j) {
        int me = 2 * j + half;
        int   sj = __shfl_sync(0xffffffffu, s, me);
        int   dj = __shfl_sync(0xffffffffu, d, me);
        float wj = __shfl_sync(0xffffffffu, w, me);
        float4 v = __ldg(&h4[(size_t)sj * 16 + fl]);
        red_add_v4(&out4[(size_t)dj * 16 + fl], v.x * wj, v.y * wj, v.z * wj, v.w * wj);
    }
}

// ---------------------------------------------------------------------------
// Fused: z = (dropout(relu(S2 @ W1 + b1))) @ W2, written to g_S1.
// Block handles 64 rows; W1 (64KB) in smem for stage 1, then W2 (32KB) overlays
// the same smem for stage 2; H tile (64 x 129, padded) lives at +64KB.
#define RB   64
#define HPAD 129
#define FUSED_SMEM ((16384 + RB * HPAD) * 4)

__device__ __forceinline__ float f4get(const float4& v, int k) {
    switch (k) { case 0: return v.x; case 1: return v.y; case 2: return v.z; default: return v.w; }
}
__device__ __forceinline__ void fma16(float* a, float xs, float4 w0, float4 w1, float4 w2, float4 w3) {
    a[0]  += xs * w0.x; a[1]  += xs * w0.y; a[2]  += xs * w0.z; a[3]  += xs * w0.w;
    a[4]  += xs * w1.x; a[5]  += xs * w1.y; a[6]  += xs * w1.z; a[7]  += xs * w1.w;
    a[8]  += xs * w2.x; a[9]  += xs * w2.y; a[10] += xs * w2.z; a[11] += xs * w2.w;
    a[12] += xs * w3.x; a[13] += xs * w3.y; a[14] += xs * w3.z; a[15] += xs * w3.w;
}

__global__ __launch_bounds__(256) void fused_kernel(const float* __restrict__ b1,
                                                    const float* __restrict__ W1,
                                                    const float* __restrict__ W2, int n) {
    extern __shared__ float sm[];
    float* W1s = sm;            // 128x128 (stage 1)
    float* W2s = sm;            // 128x64 overlays W1s (stage 2)
    float* Hs  = sm + 16384;    // RB x HPAD

    int tid = threadIdx.x;
    {   // load W1 (4096 float4)
        float4* d4 = (float4*)W1s;
        const float4* s4 = (const float4*)W1;
#pragma unroll
        for (int i = 0; i < 16; ++i) d4[tid + i * 256] = s4[tid + i * 256];
    }
    __syncthreads();

    int cg = tid & 7;            // column group: cols [cg*16, cg*16+16)
    int rg = tid >> 3;           // row group: rows rg*2, rg*2+1
    int c0 = cg * 16;
    int row0 = blockIdx.x * RB + rg * 2;
    bool ok0 = (row0 < n), ok1 = (row0 + 1 < n);

    float acc[2][16];
#pragma unroll
    for (int i = 0; i < 2; ++i)
#pragma unroll
        for (int j = 0; j < 16; ++j) acc[i][j] = 0.f;

    const float4* r0p = ((const float4*)g_S2) + (size_t)row0 * 32;
    const float4* r1p = ((const float4*)g_S2) + (size_t)(row0 + 1) * 32;

    // Stage 1: acc = S2_rows @ W1
    for (int kk = 0; kk < 32; ++kk) {
        float4 xq0 = ok0 ? __ldg(r0p + kk) : make_float4(0.f, 0.f, 0.f, 0.f);
        float4 xq1 = ok1 ? __ldg(r1p + kk) : make_float4(0.f, 0.f, 0.f, 0.f);
#pragma unroll
        for (int k4 = 0; k4 < 4; ++k4) {
            const float4* wr = (const float4*)(W1s + (kk * 4 + k4) * 128 + c0);
            float4 w0 = wr[0], w1 = wr[1], w2 = wr[2], w3 = wr[3];
            fma16(acc[0], f4get(xq0, k4), w0, w1, w2, w3);
            fma16(acc[1], f4get(xq1, k4), w0, w1, w2, w3);
        }
    }

    // bias + relu + dropout (exact JAX partitionable-threefry mask) -> Hs
    {
        float barr[16];
        float4 t0 = __ldg((const float4*)(b1 + c0));
        float4 t1 = __ldg((const float4*)(b1 + c0 + 4));
        float4 t2 = __ldg((const float4*)(b1 + c0 + 8));
        float4 t3 = __ldg((const float4*)(b1 + c0 + 12));
        barr[0]=t0.x; barr[1]=t0.y; barr[2]=t0.z; barr[3]=t0.w;
        barr[4]=t1.x; barr[5]=t1.y; barr[6]=t1.z; barr[7]=t1.w;
        barr[8]=t2.x; barr[9]=t2.y; barr[10]=t2.z; barr[11]=t2.w;
        barr[12]=t3.x; barr[13]=t3.y; barr[14]=t3.z; barr[15]=t3.w;

        unsigned m0 = ok0 ? g_mask[row0 * 4 + (cg >> 1)] : 0u;
        unsigned m1 = ok1 ? g_mask[(row0 + 1) * 4 + (cg >> 1)] : 0u;
        int sh = (cg & 1) * 16;
        float* h0 = Hs + (rg * 2 + 0) * HPAD + c0;
        float* h1 = Hs + (rg * 2 + 1) * HPAD + c0;
#pragma unroll
        for (int j = 0; j < 16; ++j) {
            float a0 = fmaxf(acc[0][j] + barr[j], 0.f);
            float a1 = fmaxf(acc[1][j] + barr[j], 0.f);
            h0[j] = ((m0 >> (sh + j)) & 1u) ? a0 * 2.f : 0.f;  // keep/(1-p), p=0.5
            h1[j] = ((m1 >> (sh + j)) & 1u) ? a1 * 2.f : 0.f;
        }
    }
    __syncthreads();

    {   // overlay-load W2 (2048 float4) into the W1 smem region
        float4* d4 = (float4*)W2s;
        const float4* s4 = (const float4*)W2;
#pragma unroll
        for (int i = 0; i < 8; ++i) d4[tid + i * 256] = s4[tid + i * 256];
    }
    __syncthreads();

    // Stage 2: z = Hs @ W2 (rows rg*2..+1, cols cg*8..+7)
    float z0[8], z1[8];
#pragma unroll
    for (int j = 0; j < 8; ++j) { z0[j] = 0.f; z1[j] = 0.f; }
    const float* h0p = Hs + (rg * 2 + 0) * HPAD;
    const float* h1p = Hs + (rg * 2 + 1) * HPAD;
#pragma unroll 4
    for (int k = 0; k < 128; ++k) {
        float4 wa = *(const float4*)(W2s + k * 64 + cg * 8);
        float4 wb = *(const float4*)(W2s + k * 64 + cg * 8 + 4);
        float ha = h0p[k], hb = h1p[k];
        z0[0]+=ha*wa.x; z0[1]+=ha*wa.y; z0[2]+=ha*wa.z; z0[3]+=ha*wa.w;
        z0[4]+=ha*wb.x; z0[5]+=ha*wb.y; z0[6]+=ha*wb.z; z0[7]+=ha*wb.w;
        z1[0]+=hb*wa.x; z1[1]+=hb*wa.y; z1[2]+=hb*wa.z; z1[3]+=hb*wa.w;
        z1[4]+=hb*wb.x; z1[5]+=hb*wb.y; z1[6]+=hb*wb.z; z1[7]+=hb*wb.w;
    }
    if (ok0) {
        float4* o = (float4*)(g_S1 + (size_t)row0 * 64 + cg * 8);
        o[0] = make_float4(z0[0], z0[1], z0[2], z0[3]);
        o[1] = make_float4(z0[4], z0[5], z0[6], z0[7]);
    }
    if (ok1) {
        float4* o = (float4*)(g_S1 + (size_t)(row0 + 1) * 64 + cg * 8);
        o[0] = make_float4(z1[0], z1[1], z1[2], z1[3]);
        o[1] = make_float4(z1[4], z1[5], z1[6], z1[7]);
    }
}

// ---------------------------------------------------------------------------
extern "C" void kernel_launch(void* const* d_in, const int* in_sizes, int n_in,
                              void* d_out, int out_size) {
    const float* x  = (const float*)d_in[0];
    const float* ew = (const float*)d_in[1];
    const float* W1 = (const float*)d_in[2];
    const float* b1 = (const float*)d_in[3];
    const float* W2 = (const float*)d_in[4];
    const float* b2 = (const float*)d_in[5];
    const int*  src = (const int*)d_in[6];
    const int*  dst = (const int*)d_in[7];
    (void)n_in; (void)out_size;

    int N = in_sizes[0] / 128;
    int E = in_sizes[1];

    cudaFuncSetAttribute(fused_kernel, cudaFuncAttributeMaxDynamicSharedMemorySize, FUSED_SMEM);

    // 1) zero layer-1 accumulator
    int n4 = N * 32;
    zero_s2_kernel<<<(n4 + 255) / 256, 256>>>(n4);
    // 2) dropout keep-mask (exact JAX partitionable threefry)
    int nwords = N * 4;
    mask_kernel<<<(nwords + 255) / 256, 256>>>(nwords);
    // 3) d_out = b2 (bias folded into init; spmm2 accumulates on top)
    init_out_kernel<<<(N * 16 + 255) / 256, 256>>>((float4*)d_out, b2, N);
    // 4) spmm1: S2 = A @ x
    spmm128_kernel<<<(E + 255) / 256, 256>>>((const float4*)x, ew, src, dst, E);
    // 5) fused: S1 = dropout(relu(S2@W1+b1)) @ W2
    fused_kernel<<<(N + RB - 1) / RB, 256, FUSED_SMEM>>>(b1, W1, W2, N);
    // 6) spmm2: d_out += A @ S1
    spmm64_kernel<<<(E + 255) / 256, 256>>>(ew, src, dst, (float4*)d_out, E);
}